// round 2
// baseline (speedup 1.0000x reference)
#include <cuda_runtime.h>

namespace {
constexpr int kB = 8, kS = 2048, kD = 512;
constexpr int BQ = 64, BK = 64, DC = 64, NCH = kD / DC;   // 8 d-chunks
constexpr int QS_STR = 516;   // pad so row-broadcast scalar reads avoid conflicts
constexpr int PS_STR = 65;
constexpr int QS_SZ = BQ * QS_STR;   // 33024 floats
constexpr int KS_SZ = BK * DC;       // 4096 (transposed + swizzled)
constexpr int VS_SZ = BK * DC;       // 4096 (row-major + swizzled)
constexpr int PS_SZ = BQ * PS_STR;   // 4160
constexpr int SMEM_BYTES = (QS_SZ + KS_SZ + VS_SZ + PS_SZ) * 4;  // 181504 B
constexpr float NEGM = -1e9f;
}

__global__ __launch_bounds__(256, 1)
void fa_fp32(const float* __restrict__ X, const int* __restrict__ msk,
             float* __restrict__ out)
{
    extern __shared__ float sm[];
    float* Qs  = sm;
    float* Kst = Qs + QS_SZ;    // [d][krow] transposed, XOR-swizzled
    float* Vs  = Kst + KS_SZ;   // [krow][d] row-major, XOR-swizzled
    float* Ps  = Vs + VS_SZ;    // [qrow][k], stride 65

    const int tid = threadIdx.x;
    const int tx = tid & 15;        // 16 col-groups
    const int ty = tid >> 4;        // 16 row-groups
    const int bid = blockIdx.x;
    const int qt = (kS / BQ - 1) - (bid >> 3);   // heavy (late) q-tiles first
    const int b  = bid & 7;
    const int q0 = qt * BQ;
    const float* Xb = X + (size_t)b * kS * kD;

    // ---- Q tile (64 x 512) -> smem, loaded once per block ----
#pragma unroll
    for (int i = 0; i < 32; ++i) {
        int fid = tid + i * 256;
        int row = fid >> 7;          // 128 float4 per row
        int c4  = fid & 127;
        float4 v = *(const float4*)(Xb + (size_t)(q0 + row) * kD + c4 * 4);
        float* dst = Qs + row * QS_STR + c4 * 4;
        dst[0] = v.x; dst[1] = v.y; dst[2] = v.z; dst[3] = v.w;
    }

    // O accumulator: rows 4*ty+m, cols c*64 + 4*tx + n  (128 regs/thread)
    float oacc[4][NCH][4];
#pragma unroll
    for (int m = 0; m < 4; ++m)
#pragma unroll
        for (int c = 0; c < NCH; ++c)
#pragma unroll
            for (int n = 0; n < 4; ++n) oacc[m][c][n] = 0.f;

    float mrow[4], lrow[4];
#pragma unroll
    for (int m = 0; m < 4; ++m) { mrow[m] = -1e30f; lrow[m] = 0.f; }

    __syncthreads();

    for (int kt = 0; kt <= qt; ++kt) {
        const int k0 = kt * BK;

        // padding mask for this thread's 4 key columns (additive, like reference)
        float padf[4];
#pragma unroll
        for (int n = 0; n < 4; ++n)
            padf[n] = msk[b * kS + k0 + 4 * tx + n] ? 0.f : NEGM;

        float sacc[4][4];
#pragma unroll
        for (int m = 0; m < 4; ++m)
#pragma unroll
            for (int n = 0; n < 4; ++n) sacc[m][n] = 0.f;

        // ================= QK^T over 8 d-chunks =================
        float4 pf[4];
#pragma unroll
        for (int i = 0; i < 4; ++i) {               // prefetch chunk 0
            int fid = tid + i * 256;
            int kr = fid >> 4, c4 = fid & 15;
            pf[i] = *(const float4*)(Xb + (size_t)(k0 + kr) * kD + c4 * 4);
        }
        for (int c = 0; c < NCH; ++c) {
            __syncthreads();                        // prior chunk reads done
            // store K chunk TRANSPOSED + swizzled: elem [dl][kr]
#pragma unroll
            for (int i = 0; i < 4; ++i) {
                int fid = tid + i * 256;
                int kr = fid >> 4, c4 = fid & 15;
                float vv[4] = {pf[i].x, pf[i].y, pf[i].z, pf[i].w};
#pragma unroll
                for (int j = 0; j < 4; ++j) {
                    int dl = c4 * 4 + j;            // dl>>2 == c4
                    Kst[dl * 64 + (((kr >> 2) ^ c4) << 2) + (kr & 3)] = vv[j];
                }
            }
            __syncthreads();
            if (c + 1 < NCH) {                      // prefetch next chunk (hides L2 lat)
#pragma unroll
                for (int i = 0; i < 4; ++i) {
                    int fid = tid + i * 256;
                    int kr = fid >> 4, c4 = fid & 15;
                    pf[i] = *(const float4*)(Xb + (size_t)(k0 + kr) * kD + (c + 1) * DC + c4 * 4);
                }
            }
            const float* qp = Qs + (4 * ty) * QS_STR + c * DC;
#pragma unroll 8
            for (int d = 0; d < DC; ++d) {
                float av[4];
#pragma unroll
                for (int m = 0; m < 4; ++m) av[m] = qp[m * QS_STR + d];
                float4 bq = *(const float4*)(Kst + d * 64 + ((tx ^ (d >> 2)) << 2));
                float bvv[4] = {bq.x, bq.y, bq.z, bq.w};
#pragma unroll
                for (int m = 0; m < 4; ++m)
#pragma unroll
                    for (int n = 0; n < 4; ++n) sacc[m][n] += av[m] * bvv[n];
            }
        }

        // ================= masks + online softmax =================
        float alpha[4];
#pragma unroll
        for (int m = 0; m < 4; ++m) {
            const int qi = q0 + 4 * ty + m;
            float rmax = -1e30f;
#pragma unroll
            for (int n = 0; n < 4; ++n) {
                int kj = k0 + 4 * tx + n;
                float s = sacc[m][n] + padf[n] + (kj > qi ? NEGM : 0.f);
                sacc[m][n] = s;
                rmax = fmaxf(rmax, s);
            }
#pragma unroll
            for (int w = 1; w < 16; w <<= 1)
                rmax = fmaxf(rmax, __shfl_xor_sync(0xffffffffu, rmax, w));
            float mn = fmaxf(mrow[m], rmax);
            alpha[m] = __expf(mrow[m] - mn);
            float rs = 0.f;
#pragma unroll
            for (int n = 0; n < 4; ++n) {
                float p = __expf(sacc[m][n] - mn);
                Ps[(4 * ty + m) * PS_STR + 4 * tx + n] = p;
                rs += p;
            }
#pragma unroll
            for (int w = 1; w < 16; w <<= 1)
                rs += __shfl_xor_sync(0xffffffffu, rs, w);
            lrow[m] = lrow[m] * alpha[m] + rs;
            mrow[m] = mn;
        }
#pragma unroll
        for (int m = 0; m < 4; ++m)
#pragma unroll
            for (int c = 0; c < NCH; ++c)
#pragma unroll
                for (int n = 0; n < 4; ++n) oacc[m][c][n] *= alpha[m];

        // ================= O += P @ V over 8 d-chunks =================
#pragma unroll
        for (int i = 0; i < 4; ++i) {               // prefetch V chunk 0
            int fid = tid + i * 256;
            int kr = fid >> 4, c4 = fid & 15;
            pf[i] = *(const float4*)(Xb + (size_t)(k0 + kr) * kD + c4 * 4);
        }
#pragma unroll
        for (int c = 0; c < NCH; ++c) {             // unrolled: oacc[..][c] stays in regs
            __syncthreads();                        // also orders Ps writes before reads (c==0)
#pragma unroll
            for (int i = 0; i < 4; ++i) {
                int fid = tid + i * 256;
                int kr = fid >> 4, c4 = fid & 15;
                *(float4*)(Vs + kr * 64 + ((c4 ^ (kr >> 2)) << 2)) = pf[i];
            }
            __syncthreads();
            if (c + 1 < NCH) {
#pragma unroll
                for (int i = 0; i < 4; ++i) {
                    int fid = tid + i * 256;
                    int kr = fid >> 4, c4 = fid & 15;
                    pf[i] = *(const float4*)(Xb + (size_t)(k0 + kr) * kD + (c + 1) * DC + c4 * 4);
                }
            }
            const float* pp = Ps + (4 * ty) * PS_STR;
#pragma unroll 4
            for (int k = 0; k < BK; ++k) {
                float av[4];
#pragma unroll
                for (int m = 0; m < 4; ++m) av[m] = pp[m * PS_STR + k];
                float4 bq = *(const float4*)(Vs + k * 64 + ((tx ^ (k >> 2)) << 2));
                float bvv[4] = {bq.x, bq.y, bq.z, bq.w};
#pragma unroll
                for (int m = 0; m < 4; ++m)
#pragma unroll
                    for (int n = 0; n < 4; ++n) oacc[m][c][n] += av[m] * bvv[n];
            }
        }
    }

    // ================= epilogue: O / l -> gmem =================
#pragma unroll
    for (int m = 0; m < 4; ++m) {
        float inv = 1.f / lrow[m];
        int row = q0 + 4 * ty + m;
        float* op = out + ((size_t)b * kS + row) * kD;
#pragma unroll
        for (int c = 0; c < NCH; ++c) {
            float4 v;
            v.x = oacc[m][c][0] * inv;
            v.y = oacc[m][c][1] * inv;
            v.z = oacc[m][c][2] * inv;
            v.w = oacc[m][c][3] * inv;
            *(float4*)(op + c * 64 + 4 * tx) = v;
        }
    }
}

extern "C" void kernel_launch(void* const* d_in, const int* in_sizes, int n_in,
                              void* d_out, int out_size)
{
    (void)out_size;
    const float* X = (const float*)d_in[0];
    const int* msk = (const int*)d_in[1];
    if (n_in >= 2 && in_sizes[0] == kB * kS) {   // defensive: inputs swapped
        X = (const float*)d_in[1];
        msk = (const int*)d_in[0];
    }
    float* out = (float*)d_out;

    cudaFuncSetAttribute(fa_fp32, cudaFuncAttributeMaxDynamicSharedMemorySize, SMEM_BYTES);
    dim3 grid(kB * (kS / BQ));   // 256 blocks, heavy q-tiles dispatched first
    fa_fp32<<<grid, 256, SMEM_BYTES>>>(X, msk, out);
}

// round 3
// speedup vs baseline: 1.0020x; 1.0020x over previous
#include <cuda_runtime.h>

namespace {
constexpr int kB = 8, kS = 2048, kD = 512;
constexpr int BQ = 64, BK = 64, DC = 64, NCH = kD / DC;   // 8 d-chunks
constexpr int QS_STR = 516;   // pad so row-broadcast scalar reads avoid conflicts
constexpr int PS_STR = 65;
constexpr int QS_SZ = BQ * QS_STR;   // 33024 floats
constexpr int KS_SZ = BK * DC;       // 4096 (transposed + swizzled)
constexpr int VS_SZ = BK * DC;       // 4096 (row-major + swizzled)
constexpr int PS_SZ = BQ * PS_STR;   // 4160
constexpr int SMEM_BYTES = (QS_SZ + KS_SZ + VS_SZ + PS_SZ) * 4;  // 181504 B
constexpr float NEGM = -1e9f;
}

__global__ __launch_bounds__(256, 1)
void fa_fp32(const float* __restrict__ X, const int* __restrict__ msk,
             float* __restrict__ out)
{
    extern __shared__ float sm[];
    float* Qs  = sm;
    float* Kst = Qs + QS_SZ;    // [d][krow] transposed, XOR-swizzled
    float* Vs  = Kst + KS_SZ;   // [krow][d] row-major, XOR-swizzled
    float* Ps  = Vs + VS_SZ;    // [qrow][k], stride 65

    const int tid = threadIdx.x;
    const int tx = tid & 15;        // 16 col-groups
    const int ty = tid >> 4;        // 16 row-groups
    const int bid = blockIdx.x;
    const int qt = (kS / BQ - 1) - (bid >> 3);   // heavy (late) q-tiles first
    const int b  = bid & 7;
    const int q0 = qt * BQ;
    const float* Xb = X + (size_t)b * kS * kD;

    // ---- Q tile (64 x 512) -> smem, loaded once per block ----
#pragma unroll
    for (int i = 0; i < 32; ++i) {
        int fid = tid + i * 256;
        int row = fid >> 7;          // 128 float4 per row
        int c4  = fid & 127;
        float4 v = *(const float4*)(Xb + (size_t)(q0 + row) * kD + c4 * 4);
        float* dst = Qs + row * QS_STR + c4 * 4;
        dst[0] = v.x; dst[1] = v.y; dst[2] = v.z; dst[3] = v.w;
    }

    // O accumulator: rows 4*ty+m, cols c*64 + 4*tx + n  (128 regs/thread)
    float oacc[4][NCH][4];
#pragma unroll
    for (int m = 0; m < 4; ++m)
#pragma unroll
        for (int c = 0; c < NCH; ++c)
#pragma unroll
            for (int n = 0; n < 4; ++n) oacc[m][c][n] = 0.f;

    float mrow[4], lrow[4];
#pragma unroll
    for (int m = 0; m < 4; ++m) { mrow[m] = -1e30f; lrow[m] = 0.f; }

    __syncthreads();

    for (int kt = 0; kt <= qt; ++kt) {
        const int k0 = kt * BK;

        // padding mask for this thread's 4 key columns (additive, like reference)
        float padf[4];
#pragma unroll
        for (int n = 0; n < 4; ++n)
            padf[n] = msk[b * kS + k0 + 4 * tx + n] ? 0.f : NEGM;

        float sacc[4][4];
#pragma unroll
        for (int m = 0; m < 4; ++m)
#pragma unroll
            for (int n = 0; n < 4; ++n) sacc[m][n] = 0.f;

        // ================= QK^T over 8 d-chunks =================
        float4 pf[4];
#pragma unroll
        for (int i = 0; i < 4; ++i) {               // prefetch chunk 0
            int fid = tid + i * 256;
            int kr = fid >> 4, c4 = fid & 15;
            pf[i] = *(const float4*)(Xb + (size_t)(k0 + kr) * kD + c4 * 4);
        }
        for (int c = 0; c < NCH; ++c) {
            __syncthreads();                        // prior chunk reads done
            // store K chunk TRANSPOSED + swizzled: elem [dl][kr]
#pragma unroll
            for (int i = 0; i < 4; ++i) {
                int fid = tid + i * 256;
                int kr = fid >> 4, c4 = fid & 15;
                float vv[4] = {pf[i].x, pf[i].y, pf[i].z, pf[i].w};
#pragma unroll
                for (int j = 0; j < 4; ++j) {
                    int dl = c4 * 4 + j;            // dl>>2 == c4
                    Kst[dl * 64 + (((kr >> 2) ^ c4) << 2) + (kr & 3)] = vv[j];
                }
            }
            __syncthreads();
            if (c + 1 < NCH) {                      // prefetch next chunk (hides L2 lat)
#pragma unroll
                for (int i = 0; i < 4; ++i) {
                    int fid = tid + i * 256;
                    int kr = fid >> 4, c4 = fid & 15;
                    pf[i] = *(const float4*)(Xb + (size_t)(k0 + kr) * kD + (c + 1) * DC + c4 * 4);
                }
            }
            const float* qp = Qs + (4 * ty) * QS_STR + c * DC;
#pragma unroll 8
            for (int d = 0; d < DC; ++d) {
                float av[4];
#pragma unroll
                for (int m = 0; m < 4; ++m) av[m] = qp[m * QS_STR + d];
                float4 bq = *(const float4*)(Kst + d * 64 + ((tx ^ (d >> 2)) << 2));
                float bvv[4] = {bq.x, bq.y, bq.z, bq.w};
#pragma unroll
                for (int m = 0; m < 4; ++m)
#pragma unroll
                    for (int n = 0; n < 4; ++n) sacc[m][n] += av[m] * bvv[n];
            }
        }

        // ================= masks + online softmax =================
        float alpha[4];
#pragma unroll
        for (int m = 0; m < 4; ++m) {
            const int qi = q0 + 4 * ty + m;
            float rmax = -1e30f;
#pragma unroll
            for (int n = 0; n < 4; ++n) {
                int kj = k0 + 4 * tx + n;
                float s = sacc[m][n] + padf[n] + (kj > qi ? NEGM : 0.f);
                sacc[m][n] = s;
                rmax = fmaxf(rmax, s);
            }
#pragma unroll
            for (int w = 1; w < 16; w <<= 1)
                rmax = fmaxf(rmax, __shfl_xor_sync(0xffffffffu, rmax, w));
            float mn = fmaxf(mrow[m], rmax);
            alpha[m] = __expf(mrow[m] - mn);
            float rs = 0.f;
#pragma unroll
            for (int n = 0; n < 4; ++n) {
                float p = __expf(sacc[m][n] - mn);
                Ps[(4 * ty + m) * PS_STR + 4 * tx + n] = p;
                rs += p;
            }
#pragma unroll
            for (int w = 1; w < 16; w <<= 1)
                rs += __shfl_xor_sync(0xffffffffu, rs, w);
            lrow[m] = lrow[m] * alpha[m] + rs;
            mrow[m] = mn;
        }
#pragma unroll
        for (int m = 0; m < 4; ++m)
#pragma unroll
            for (int c = 0; c < NCH; ++c)
#pragma unroll
                for (int n = 0; n < 4; ++n) oacc[m][c][n] *= alpha[m];

        // ================= O += P @ V over 8 d-chunks =================
#pragma unroll
        for (int i = 0; i < 4; ++i) {               // prefetch V chunk 0
            int fid = tid + i * 256;
            int kr = fid >> 4, c4 = fid & 15;
            pf[i] = *(const float4*)(Xb + (size_t)(k0 + kr) * kD + c4 * 4);
        }
#pragma unroll
        for (int c = 0; c < NCH; ++c) {             // unrolled: oacc[..][c] stays in regs
            __syncthreads();                        // also orders Ps writes before reads (c==0)
#pragma unroll
            for (int i = 0; i < 4; ++i) {
                int fid = tid + i * 256;
                int kr = fid >> 4, c4 = fid & 15;
                *(float4*)(Vs + kr * 64 + ((c4 ^ (kr >> 2)) << 2)) = pf[i];
            }
            __syncthreads();
            if (c + 1 < NCH) {
#pragma unroll
                for (int i = 0; i < 4; ++i) {
                    int fid = tid + i * 256;
                    int kr = fid >> 4, c4 = fid & 15;
                    pf[i] = *(const float4*)(Xb + (size_t)(k0 + kr) * kD + (c + 1) * DC + c4 * 4);
                }
            }
            const float* pp = Ps + (4 * ty) * PS_STR;
#pragma unroll 4
            for (int k = 0; k < BK; ++k) {
                float av[4];
#pragma unroll
                for (int m = 0; m < 4; ++m) av[m] = pp[m * PS_STR + k];
                float4 bq = *(const float4*)(Vs + k * 64 + ((tx ^ (k >> 2)) << 2));
                float bvv[4] = {bq.x, bq.y, bq.z, bq.w};
#pragma unroll
                for (int m = 0; m < 4; ++m)
#pragma unroll
                    for (int n = 0; n < 4; ++n) oacc[m][c][n] += av[m] * bvv[n];
            }
        }
    }

    // ================= epilogue: O / l -> gmem =================
#pragma unroll
    for (int m = 0; m < 4; ++m) {
        float inv = 1.f / lrow[m];
        int row = q0 + 4 * ty + m;
        float* op = out + ((size_t)b * kS + row) * kD;
#pragma unroll
        for (int c = 0; c < NCH; ++c) {
            float4 v;
            v.x = oacc[m][c][0] * inv;
            v.y = oacc[m][c][1] * inv;
            v.z = oacc[m][c][2] * inv;
            v.w = oacc[m][c][3] * inv;
            *(float4*)(op + c * 64 + 4 * tx) = v;
        }
    }
}

extern "C" void kernel_launch(void* const* d_in, const int* in_sizes, int n_in,
                              void* d_out, int out_size)
{
    (void)out_size;
    const float* X = (const float*)d_in[0];
    const int* msk = (const int*)d_in[1];
    if (n_in >= 2 && in_sizes[0] == kB * kS) {   // defensive: inputs swapped
        X = (const float*)d_in[1];
        msk = (const int*)d_in[0];
    }
    float* out = (float*)d_out;

    cudaFuncSetAttribute(fa_fp32, cudaFuncAttributeMaxDynamicSharedMemorySize, SMEM_BYTES);
    dim3 grid(kB * (kS / BQ));   // 256 blocks, heavy q-tiles dispatched first
    fa_fp32<<<grid, 256, SMEM_BYTES>>>(X, msk, out);
}

// round 4
// speedup vs baseline: 1.0048x; 1.0028x over previous
#include <cuda_runtime.h>

namespace {
constexpr int kB = 8, kS = 2048, kD = 512;
constexpr int BQ = 64, BK = 64, DC = 64, NCH = kD / DC;   // 8 d-chunks
constexpr int QS_STR = 516;   // pad so row-broadcast scalar reads avoid conflicts
constexpr int PS_STR = 65;
constexpr int QS_SZ = BQ * QS_STR;   // 33024 floats
constexpr int KS_SZ = BK * DC;       // 4096 (transposed + swizzled)
constexpr int VS_SZ = BK * DC;       // 4096 (row-major + swizzled)
constexpr int PS_SZ = BQ * PS_STR;   // 4160
constexpr int SMEM_BYTES = (QS_SZ + KS_SZ + VS_SZ + PS_SZ) * 4;  // 181504 B
constexpr float NEGM = -1e9f;
}

__global__ __launch_bounds__(256, 1)
void fa_fp32(const float* __restrict__ X, const int* __restrict__ msk,
             float* __restrict__ out)
{
    extern __shared__ float sm[];
    float* Qs  = sm;
    float* Kst = Qs + QS_SZ;    // [d][krow] transposed, XOR-swizzled
    float* Vs  = Kst + KS_SZ;   // [krow][d] row-major, XOR-swizzled
    float* Ps  = Vs + VS_SZ;    // [qrow][k], stride 65

    const int tid = threadIdx.x;
    const int tx = tid & 15;        // 16 col-groups
    const int ty = tid >> 4;        // 16 row-groups
    const int bid = blockIdx.x;
    const int qt = (kS / BQ - 1) - (bid >> 3);   // heavy (late) q-tiles first
    const int b  = bid & 7;
    const int q0 = qt * BQ;
    const float* Xb = X + (size_t)b * kS * kD;

    // ---- Q tile (64 x 512) -> smem, loaded once per block ----
#pragma unroll
    for (int i = 0; i < 32; ++i) {
        int fid = tid + i * 256;
        int row = fid >> 7;          // 128 float4 per row
        int c4  = fid & 127;
        float4 v = *(const float4*)(Xb + (size_t)(q0 + row) * kD + c4 * 4);
        float* dst = Qs + row * QS_STR + c4 * 4;
        dst[0] = v.x; dst[1] = v.y; dst[2] = v.z; dst[3] = v.w;
    }

    // O accumulator: rows 4*ty+m, cols c*64 + 4*tx + n  (128 regs/thread)
    float oacc[4][NCH][4];
#pragma unroll
    for (int m = 0; m < 4; ++m)
#pragma unroll
        for (int c = 0; c < NCH; ++c)
#pragma unroll
            for (int n = 0; n < 4; ++n) oacc[m][c][n] = 0.f;

    float mrow[4], lrow[4];
#pragma unroll
    for (int m = 0; m < 4; ++m) { mrow[m] = -1e30f; lrow[m] = 0.f; }

    __syncthreads();

    for (int kt = 0; kt <= qt; ++kt) {
        const int k0 = kt * BK;

        // padding mask for this thread's 4 key columns (additive, like reference)
        float padf[4];
#pragma unroll
        for (int n = 0; n < 4; ++n)
            padf[n] = msk[b * kS + k0 + 4 * tx + n] ? 0.f : NEGM;

        float sacc[4][4];
#pragma unroll
        for (int m = 0; m < 4; ++m)
#pragma unroll
            for (int n = 0; n < 4; ++n) sacc[m][n] = 0.f;

        // ================= QK^T over 8 d-chunks =================
        float4 pf[4];
#pragma unroll
        for (int i = 0; i < 4; ++i) {               // prefetch chunk 0
            int fid = tid + i * 256;
            int kr = fid >> 4, c4 = fid & 15;
            pf[i] = *(const float4*)(Xb + (size_t)(k0 + kr) * kD + c4 * 4);
        }
        for (int c = 0; c < NCH; ++c) {
            __syncthreads();                        // prior chunk reads done
            // store K chunk TRANSPOSED + swizzled: elem [dl][kr]
#pragma unroll
            for (int i = 0; i < 4; ++i) {
                int fid = tid + i * 256;
                int kr = fid >> 4, c4 = fid & 15;
                float vv[4] = {pf[i].x, pf[i].y, pf[i].z, pf[i].w};
#pragma unroll
                for (int j = 0; j < 4; ++j) {
                    int dl = c4 * 4 + j;            // dl>>2 == c4
                    Kst[dl * 64 + (((kr >> 2) ^ c4) << 2) + (kr & 3)] = vv[j];
                }
            }
            __syncthreads();
            if (c + 1 < NCH) {                      // prefetch next chunk (hides L2 lat)
#pragma unroll
                for (int i = 0; i < 4; ++i) {
                    int fid = tid + i * 256;
                    int kr = fid >> 4, c4 = fid & 15;
                    pf[i] = *(const float4*)(Xb + (size_t)(k0 + kr) * kD + (c + 1) * DC + c4 * 4);
                }
            }
            const float* qp = Qs + (4 * ty) * QS_STR + c * DC;
#pragma unroll 8
            for (int d = 0; d < DC; ++d) {
                float av[4];
#pragma unroll
                for (int m = 0; m < 4; ++m) av[m] = qp[m * QS_STR + d];
                float4 bq = *(const float4*)(Kst + d * 64 + ((tx ^ (d >> 2)) << 2));
                float bvv[4] = {bq.x, bq.y, bq.z, bq.w};
#pragma unroll
                for (int m = 0; m < 4; ++m)
#pragma unroll
                    for (int n = 0; n < 4; ++n) sacc[m][n] += av[m] * bvv[n];
            }
        }

        // ================= masks + online softmax =================
        float alpha[4];
#pragma unroll
        for (int m = 0; m < 4; ++m) {
            const int qi = q0 + 4 * ty + m;
            float rmax = -1e30f;
#pragma unroll
            for (int n = 0; n < 4; ++n) {
                int kj = k0 + 4 * tx + n;
                float s = sacc[m][n] + padf[n] + (kj > qi ? NEGM : 0.f);
                sacc[m][n] = s;
                rmax = fmaxf(rmax, s);
            }
#pragma unroll
            for (int w = 1; w < 16; w <<= 1)
                rmax = fmaxf(rmax, __shfl_xor_sync(0xffffffffu, rmax, w));
            float mn = fmaxf(mrow[m], rmax);
            alpha[m] = __expf(mrow[m] - mn);
            float rs = 0.f;
#pragma unroll
            for (int n = 0; n < 4; ++n) {
                float p = __expf(sacc[m][n] - mn);
                Ps[(4 * ty + m) * PS_STR + 4 * tx + n] = p;
                rs += p;
            }
#pragma unroll
            for (int w = 1; w < 16; w <<= 1)
                rs += __shfl_xor_sync(0xffffffffu, rs, w);
            lrow[m] = lrow[m] * alpha[m] + rs;
            mrow[m] = mn;
        }
#pragma unroll
        for (int m = 0; m < 4; ++m)
#pragma unroll
            for (int c = 0; c < NCH; ++c)
#pragma unroll
                for (int n = 0; n < 4; ++n) oacc[m][c][n] *= alpha[m];

        // ================= O += P @ V over 8 d-chunks =================
#pragma unroll
        for (int i = 0; i < 4; ++i) {               // prefetch V chunk 0
            int fid = tid + i * 256;
            int kr = fid >> 4, c4 = fid & 15;
            pf[i] = *(const float4*)(Xb + (size_t)(k0 + kr) * kD + c4 * 4);
        }
#pragma unroll
        for (int c = 0; c < NCH; ++c) {             // unrolled: oacc[..][c] stays in regs
            __syncthreads();                        // also orders Ps writes before reads (c==0)
#pragma unroll
            for (int i = 0; i < 4; ++i) {
                int fid = tid + i * 256;
                int kr = fid >> 4, c4 = fid & 15;
                *(float4*)(Vs + kr * 64 + ((c4 ^ (kr >> 2)) << 2)) = pf[i];
            }
            __syncthreads();
            if (c + 1 < NCH) {
#pragma unroll
                for (int i = 0; i < 4; ++i) {
                    int fid = tid + i * 256;
                    int kr = fid >> 4, c4 = fid & 15;
                    pf[i] = *(const float4*)(Xb + (size_t)(k0 + kr) * kD + (c + 1) * DC + c4 * 4);
                }
            }
            const float* pp = Ps + (4 * ty) * PS_STR;
#pragma unroll 4
            for (int k = 0; k < BK; ++k) {
                float av[4];
#pragma unroll
                for (int m = 0; m < 4; ++m) av[m] = pp[m * PS_STR + k];
                float4 bq = *(const float4*)(Vs + k * 64 + ((tx ^ (k >> 2)) << 2));
                float bvv[4] = {bq.x, bq.y, bq.z, bq.w};
#pragma unroll
                for (int m = 0; m < 4; ++m)
#pragma unroll
                    for (int n = 0; n < 4; ++n) oacc[m][c][n] += av[m] * bvv[n];
            }
        }
    }

    // ================= epilogue: O / l -> gmem =================
#pragma unroll
    for (int m = 0; m < 4; ++m) {
        float inv = 1.f / lrow[m];
        int row = q0 + 4 * ty + m;
        float* op = out + ((size_t)b * kS + row) * kD;
#pragma unroll
        for (int c = 0; c < NCH; ++c) {
            float4 v;
            v.x = oacc[m][c][0] * inv;
            v.y = oacc[m][c][1] * inv;
            v.z = oacc[m][c][2] * inv;
            v.w = oacc[m][c][3] * inv;
            *(float4*)(op + c * 64 + 4 * tx) = v;
        }
    }
}

extern "C" void kernel_launch(void* const* d_in, const int* in_sizes, int n_in,
                              void* d_out, int out_size)
{
    (void)out_size;
    const float* X = (const float*)d_in[0];
    const int* msk = (const int*)d_in[1];
    if (n_in >= 2 && in_sizes[0] == kB * kS) {   // defensive: inputs swapped
        X = (const float*)d_in[1];
        msk = (const int*)d_in[0];
    }
    float* out = (float*)d_out;

    cudaFuncSetAttribute(fa_fp32, cudaFuncAttributeMaxDynamicSharedMemorySize, SMEM_BYTES);
    dim3 grid(kB * (kS / BQ));   // 256 blocks, heavy q-tiles dispatched first
    fa_fp32<<<grid, 256, SMEM_BYTES>>>(X, msk, out);
}

// round 5
// speedup vs baseline: 1.0555x; 1.0505x over previous
#include <cuda_runtime.h>

namespace {
constexpr int kB = 8, kS = 2048, kD = 512;
constexpr int BQ = 64, BK = 64, DC = 64, NCH = kD / DC;   // 8 d-chunks
constexpr int QT_STR = 64;            // Qt[d][q] transposed, 64 q per row
constexpr int PS_STR = 68;            // PsT[k][q] transposed (16B-aligned rows)
constexpr int QT_SZ = kD * QT_STR;    // 32768 floats (128 KB)
constexpr int KS_SZ = BK * DC;        // 4096 (transposed + swizzled, per chunk)
constexpr int VS_SZ = BK * DC;        // 4096 (row-major + swizzled, per chunk)
constexpr int PS_SZ = BK * PS_STR;    // 4352
constexpr int SMEM_BYTES = (QT_SZ + KS_SZ + VS_SZ + PS_SZ) * 4;  // 181248 B
constexpr float NEGM = -1e9f;
}

__global__ __launch_bounds__(256, 1)
void fa_fp32(const float* __restrict__ X, const int* __restrict__ msk,
             float* __restrict__ out)
{
    extern __shared__ float sm[];
    float* Qt  = sm;            // [d][q]   transposed Q, resident
    float* Kst = Qt + QT_SZ;    // [d][k]   transposed K chunk, XOR-swizzled
    float* Vs  = Kst + KS_SZ;   // [k][d]   V chunk, XOR-swizzled
    float* PsT = Vs + VS_SZ;    // [k][q]   transposed P, stride 68

    const int tid = threadIdx.x;
    const int tx = tid & 15;        // 16 col-groups (k / d cols)
    const int ty = tid >> 4;        // 16 row-groups (q rows)
    const int bid = blockIdx.x;
    const int qt = (kS / BQ - 1) - (bid >> 3);   // heavy (late) q-tiles first
    const int b  = bid & 7;
    const int q0 = qt * BQ;
    const float* Xb = X + (size_t)b * kS * kD;

    // ---- Q tile (64 x 512) -> smem TRANSPOSED: Qt[d][q] (one-time) ----
#pragma unroll
    for (int i = 0; i < 32; ++i) {
        int fid = tid + i * 256;
        int row = fid >> 7;          // q row (0..63), 128 float4 per row
        int c4  = fid & 127;         // d quad
        float4 v = *(const float4*)(Xb + (size_t)(q0 + row) * kD + c4 * 4);
        Qt[(c4 * 4 + 0) * QT_STR + row] = v.x;
        Qt[(c4 * 4 + 1) * QT_STR + row] = v.y;
        Qt[(c4 * 4 + 2) * QT_STR + row] = v.z;
        Qt[(c4 * 4 + 3) * QT_STR + row] = v.w;
    }

    // O accumulator: rows 4*ty+m, cols c*64 + 4*tx + n  (128 regs/thread)
    float oacc[4][NCH][4];
#pragma unroll
    for (int m = 0; m < 4; ++m)
#pragma unroll
        for (int c = 0; c < NCH; ++c)
#pragma unroll
            for (int n = 0; n < 4; ++n) oacc[m][c][n] = 0.f;

    float mrow[4], lrow[4];
#pragma unroll
    for (int m = 0; m < 4; ++m) { mrow[m] = -1e30f; lrow[m] = 0.f; }

    __syncthreads();

    for (int kt = 0; kt <= qt; ++kt) {
        const int k0 = kt * BK;

        // padding mask for this thread's 4 key columns (additive, like reference)
        float padf[4];
#pragma unroll
        for (int n = 0; n < 4; ++n)
            padf[n] = msk[b * kS + k0 + 4 * tx + n] ? 0.f : NEGM;

        float sacc[4][4];
#pragma unroll
        for (int m = 0; m < 4; ++m)
#pragma unroll
            for (int n = 0; n < 4; ++n) sacc[m][n] = 0.f;

        // ================= QK^T over 8 d-chunks =================
        float4 pf[4];
#pragma unroll
        for (int i = 0; i < 4; ++i) {               // prefetch chunk 0
            int fid = tid + i * 256;
            int kr = fid >> 4, c4 = fid & 15;
            pf[i] = *(const float4*)(Xb + (size_t)(k0 + kr) * kD + c4 * 4);
        }
        for (int c = 0; c < NCH; ++c) {
            __syncthreads();                        // prior chunk reads done
            // store K chunk TRANSPOSED + swizzled: elem [dl][kr]
#pragma unroll
            for (int i = 0; i < 4; ++i) {
                int fid = tid + i * 256;
                int kr = fid >> 4, c4 = fid & 15;
                float vv[4] = {pf[i].x, pf[i].y, pf[i].z, pf[i].w};
#pragma unroll
                for (int j = 0; j < 4; ++j) {
                    int dl = c4 * 4 + j;            // dl>>2 == c4
                    Kst[dl * 64 + (((kr >> 2) ^ c4) << 2) + (kr & 3)] = vv[j];
                }
            }
            __syncthreads();
            if (c + 1 < NCH) {                      // prefetch next chunk (hides L2 lat)
#pragma unroll
                for (int i = 0; i < 4; ++i) {
                    int fid = tid + i * 256;
                    int kr = fid >> 4, c4 = fid & 15;
                    pf[i] = *(const float4*)(Xb + (size_t)(k0 + kr) * kD + (c + 1) * DC + c4 * 4);
                }
            }
            const float* qp = Qt + (c * DC) * QT_STR + 4 * ty;
#pragma unroll 8
            for (int d = 0; d < DC; ++d) {
                float4 aq = *(const float4*)(qp + d * QT_STR);       // Q[4ty..+3][c*64+d]
                float av[4] = {aq.x, aq.y, aq.z, aq.w};
                float4 bq = *(const float4*)(Kst + d * 64 + ((tx ^ (d >> 2)) << 2));
                float bvv[4] = {bq.x, bq.y, bq.z, bq.w};
#pragma unroll
                for (int m = 0; m < 4; ++m)
#pragma unroll
                    for (int n = 0; n < 4; ++n) sacc[m][n] += av[m] * bvv[n];
            }
        }

        // ================= masks + online softmax =================
        const bool diag = (kt == qt);
        float alpha[4];
#pragma unroll
        for (int m = 0; m < 4; ++m) {
            const int qi = q0 + 4 * ty + m;
            float rmax = -1e30f;
#pragma unroll
            for (int n = 0; n < 4; ++n) {
                float s = sacc[m][n] + padf[n];
                if (diag) s += (k0 + 4 * tx + n > qi) ? NEGM : 0.f;
                sacc[m][n] = s;
                rmax = fmaxf(rmax, s);
            }
#pragma unroll
            for (int w = 1; w < 16; w <<= 1)
                rmax = fmaxf(rmax, __shfl_xor_sync(0xffffffffu, rmax, w));
            float mn = fmaxf(mrow[m], rmax);
            alpha[m] = __expf(mrow[m] - mn);
            float rs = 0.f;
#pragma unroll
            for (int n = 0; n < 4; ++n) {
                float p = __expf(sacc[m][n] - mn);
                sacc[m][n] = p;
                rs += p;
            }
#pragma unroll
            for (int w = 1; w < 16; w <<= 1)
                rs += __shfl_xor_sync(0xffffffffu, rs, w);
            lrow[m] = lrow[m] * alpha[m] + rs;
            mrow[m] = mn;
        }
        // store P TRANSPOSED: PsT[k][q], one STS.128 per n (4 q values)
#pragma unroll
        for (int n = 0; n < 4; ++n) {
            float4 pv;
            pv.x = sacc[0][n]; pv.y = sacc[1][n];
            pv.z = sacc[2][n]; pv.w = sacc[3][n];
            *(float4*)(PsT + (4 * tx + n) * PS_STR + 4 * ty) = pv;
        }
#pragma unroll
        for (int m = 0; m < 4; ++m)
#pragma unroll
            for (int c = 0; c < NCH; ++c)
#pragma unroll
                for (int n = 0; n < 4; ++n) oacc[m][c][n] *= alpha[m];

        // ================= O += P @ V over 8 d-chunks =================
#pragma unroll
        for (int i = 0; i < 4; ++i) {               // prefetch V chunk 0
            int fid = tid + i * 256;
            int kr = fid >> 4, c4 = fid & 15;
            pf[i] = *(const float4*)(Xb + (size_t)(k0 + kr) * kD + c4 * 4);
        }
#pragma unroll
        for (int c = 0; c < NCH; ++c) {             // unrolled: oacc[..][c] stays in regs
            __syncthreads();                        // also orders PsT writes before reads (c==0)
#pragma unroll
            for (int i = 0; i < 4; ++i) {
                int fid = tid + i * 256;
                int kr = fid >> 4, c4 = fid & 15;
                *(float4*)(Vs + kr * 64 + ((c4 ^ (kr >> 2)) << 2)) = pf[i];
            }
            __syncthreads();
            if (c + 1 < NCH) {
#pragma unroll
                for (int i = 0; i < 4; ++i) {
                    int fid = tid + i * 256;
                    int kr = fid >> 4, c4 = fid & 15;
                    pf[i] = *(const float4*)(Xb + (size_t)(k0 + kr) * kD + (c + 1) * DC + c4 * 4);
                }
            }
            const float* pp = PsT + 4 * ty;
#pragma unroll 4
            for (int k = 0; k < BK; ++k) {
                float4 ap = *(const float4*)(pp + k * PS_STR);       // P[4ty..+3][k]
                float av[4] = {ap.x, ap.y, ap.z, ap.w};
                float4 bq = *(const float4*)(Vs + k * 64 + ((tx ^ (k >> 2)) << 2));
                float bvv[4] = {bq.x, bq.y, bq.z, bq.w};
#pragma unroll
                for (int m = 0; m < 4; ++m)
#pragma unroll
                    for (int n = 0; n < 4; ++n) oacc[m][c][n] += av[m] * bvv[n];
            }
        }
    }

    // ================= epilogue: O / l -> gmem =================
#pragma unroll
    for (int m = 0; m < 4; ++m) {
        float inv = 1.f / lrow[m];
        int row = q0 + 4 * ty + m;
        float* op = out + ((size_t)b * kS + row) * kD;
#pragma unroll
        for (int c = 0; c < NCH; ++c) {
            float4 v;
            v.x = oacc[m][c][0] * inv;
            v.y = oacc[m][c][1] * inv;
            v.z = oacc[m][c][2] * inv;
            v.w = oacc[m][c][3] * inv;
            *(float4*)(op + c * 64 + 4 * tx) = v;
        }
    }
}

extern "C" void kernel_launch(void* const* d_in, const int* in_sizes, int n_in,
                              void* d_out, int out_size)
{
    (void)out_size;
    const float* X = (const float*)d_in[0];
    const int* msk = (const int*)d_in[1];
    if (n_in >= 2 && in_sizes[0] == kB * kS) {   // defensive: inputs swapped
        X = (const float*)d_in[1];
        msk = (const int*)d_in[0];
    }
    float* out = (float*)d_out;

    cudaFuncSetAttribute(fa_fp32, cudaFuncAttributeMaxDynamicSharedMemorySize, SMEM_BYTES);
    dim3 grid(kB * (kS / BQ));   // 256 blocks, heavy q-tiles dispatched first
    fa_fp32<<<grid, 256, SMEM_BYTES>>>(X, msk, out);
}